// round 1
// baseline (speedup 1.0000x reference)
#include <cuda_runtime.h>
#include <cstdint>
#include <cstddef>

// Problem constants (fixed by the dataset)
#define MAX_E2 1000000

// ---------------------------------------------------------------------------
// Scratch (device globals; allocation inside kernel_launch is forbidden)
// ---------------------------------------------------------------------------
__device__ float g_S0[(size_t)MAX_E2 * 64];
__device__ float g_S1[(size_t)MAX_E2 * 64];
__device__ float g_S2[(size_t)MAX_E2 * 64];
__device__ float g_M [(size_t)MAX_E2 * 64];
__device__ float g_P [(size_t)MAX_E2 * 64];
__device__ int   g_c0[MAX_E2];
__device__ int   g_c1[MAX_E2];
__device__ int   g_c2[MAX_E2];
__device__ int   g_is64;

// ---------------------------------------------------------------------------
// Helpers
// ---------------------------------------------------------------------------
__device__ __forceinline__ long long ldidx(const void* b, long long i, int is64) {
    if (is64) return ((const long long*)b)[i];
    return (long long)((const int*)b)[i];
}

__device__ __forceinline__ void fma2(unsigned long long& a,
                                     unsigned long long x,
                                     unsigned long long w) {
    asm("fma.rn.f32x2 %0, %1, %2, %0;" : "+l"(a) : "l"(x), "l"(w));
}

__device__ __forceinline__ float2 hadd2(unsigned long long a) {
    float lo, hi;
    asm("mov.b64 {%0, %1}, %2;" : "=f"(lo), "=f"(hi) : "l"(a));
    return make_float2(lo, hi);
}

// 4-row batched 64x64 GEMV. xw: 4 rows of 64 floats (smem). Ws: weight matrix
// in pair-interleaved layout Ws[kp*64 + j] = (W[2kp][j], W[2kp+1][j]).
// Lane l produces outputs for columns l and l+32 of each row.
__device__ __forceinline__ void wgemv4(const float* xw, const float2* Ws, int l,
                                       float2 out[4]) {
    unsigned long long a0[4] = {0, 0, 0, 0};
    unsigned long long a1[4] = {0, 0, 0, 0};
#pragma unroll
    for (int kp = 0; kp < 32; ++kp) {
        unsigned long long w0 = *(const unsigned long long*)(Ws + kp * 64 + l);
        unsigned long long w1 = *(const unsigned long long*)(Ws + kp * 64 + l + 32);
#pragma unroll
        for (int r = 0; r < 4; ++r) {
            unsigned long long xp = *(const unsigned long long*)(xw + r * 64 + 2 * kp);
            fma2(a0[r], xp, w0);
            fma2(a1[r], xp, w1);
        }
    }
#pragma unroll
    for (int r = 0; r < 4; ++r) {
        float2 u = hadd2(a0[r]);
        float2 v = hadd2(a1[r]);
        out[r] = make_float2(u.x + u.y, v.x + v.y);
    }
}

// ---------------------------------------------------------------------------
// Index dtype detection: if the index arrays are int64, every odd 32-bit word
// (high word) of the first 128 entries is 0. If int32, those words are random
// indices in [0, 500000) and cannot all be zero.
// ---------------------------------------------------------------------------
__global__ void detect_kernel(const int* __restrict__ p) {
    if (threadIdx.x == 0 && blockIdx.x == 0) {
        int acc = 0;
#pragma unroll 1
        for (int i = 0; i < 128; ++i) acc |= p[2 * i + 1];
        g_is64 = (acc == 0) ? 1 : 0;
    }
}

// ---------------------------------------------------------------------------
// Scatter: for each triangle t, S[idxS[t]] += srcA[idxA[t]] + srcB[idxB[t]],
// cnt[idxS[t]] += 1. 16 threads per triangle, float4 lanes, vector red atomics.
// ---------------------------------------------------------------------------
__global__ __launch_bounds__(256) void scatter_kernel(
    const void* __restrict__ tri,
    long long offS, long long offA, long long offB,
    const float* __restrict__ srcA, const float* __restrict__ srcB,
    float* __restrict__ S, int* __restrict__ cnt, int T)
{
    long long g = (long long)blockIdx.x * blockDim.x + threadIdx.x;
    long long t = g >> 4;
    int c = (int)(g & 15);
    if (t >= (long long)T) return;
    int is64 = g_is64;
    long long s = ldidx(tri, offS + t, is64);
    long long a = ldidx(tri, offA + t, is64);
    long long b = ldidx(tri, offB + t, is64);
    float4 va = __ldg((const float4*)(srcA + a * 64) + c);
    float4 vb = __ldg((const float4*)(srcB + b * 64) + c);
    float4 v = make_float4(va.x + vb.x, va.y + vb.y, va.z + vb.z, va.w + vb.w);
    float* dst = S + s * 64 + c * 4;
    asm volatile("red.global.add.v4.f32 [%0], {%1,%2,%3,%4};"
                 :: "l"(dst), "f"(v.x), "f"(v.y), "f"(v.z), "f"(v.w) : "memory");
    if (c == 0) atomicAdd(cnt + s, 1);
}

// ---------------------------------------------------------------------------
// Combine: M[e] = S1[e]@W1 + c1[e]*b1
//          P[e] = base[e] + S0[e]@W0 + c0*b0 + S2[e]@W2 + c2*b2 + M[e]
// Warp processes 4 rows at a time; all three 64x64 weights staged in smem.
// ---------------------------------------------------------------------------
#define COMB_SMEM (3 * 2048 * 8 + 192 * 4 + 8 * 256 * 4)

__global__ __launch_bounds__(256) void combine_kernel(
    const float* __restrict__ S0, const float* __restrict__ S1, const float* __restrict__ S2,
    const int* __restrict__ c0, const int* __restrict__ c1, const int* __restrict__ c2,
    const float* __restrict__ Wp, const float* __restrict__ bp, int wOff,
    const float* __restrict__ base, float* __restrict__ M, float* __restrict__ P,
    int N)
{
    extern __shared__ float smem[];
    float2* Ws0 = (float2*)smem;
    float2* Ws1 = Ws0 + 2048;
    float2* Ws2 = Ws1 + 2048;
    float*  bsh = (float*)(Ws2 + 2048);   // 192 floats
    float*  xbase = bsh + 192;            // 8 warps * 256 floats

    int tid = threadIdx.x;
    const float* W = Wp + (size_t)wOff * 4096;
    for (int i = tid; i < 2048; i += blockDim.x) {
        int kp = i >> 6, j = i & 63;
        Ws0[i] = make_float2(W[(2 * kp) * 64 + j],        W[(2 * kp + 1) * 64 + j]);
        Ws1[i] = make_float2(W[4096 + (2 * kp) * 64 + j], W[4096 + (2 * kp + 1) * 64 + j]);
        Ws2[i] = make_float2(W[8192 + (2 * kp) * 64 + j], W[8192 + (2 * kp + 1) * 64 + j]);
    }
    for (int i = tid; i < 192; i += blockDim.x) bsh[i] = bp[wOff * 64 + i];
    __syncthreads();

    int wid = tid >> 5, l = tid & 31;
    float* xw = xbase + wid * 256;
    float b0l = bsh[l],       b0h = bsh[l + 32];
    float b1l = bsh[64 + l],  b1h = bsh[96 + l];
    float b2l = bsh[128 + l], b2h = bsh[160 + l];

    long long gw   = (long long)blockIdx.x * (blockDim.x >> 5) + wid;
    long long totW = (long long)gridDim.x * (blockDim.x >> 5);

    for (long long bb = gw * 4; bb < (long long)N; bb += totW * 4) {
        float2 acc[4];
        // --- S0 @ W0
#pragma unroll
        for (int r = 0; r < 4; ++r) {
            long long row = bb + r;
            long long src = (row < (long long)N) ? row : bb;
            xw[r * 64 + l]      = S0[src * 64 + l];
            xw[r * 64 + l + 32] = S0[src * 64 + l + 32];
        }
        __syncwarp();
        {
            float2 o[4]; wgemv4(xw, Ws0, l, o);
#pragma unroll
            for (int r = 0; r < 4; ++r) {
                long long row = bb + r;
                float n0 = (row < (long long)N) ? (float)c0[row] : 0.f;
                acc[r].x = o[r].x + n0 * b0l;
                acc[r].y = o[r].y + n0 * b0h;
            }
        }
        __syncwarp();
        // --- S2 @ W2
#pragma unroll
        for (int r = 0; r < 4; ++r) {
            long long row = bb + r;
            long long src = (row < (long long)N) ? row : bb;
            xw[r * 64 + l]      = S2[src * 64 + l];
            xw[r * 64 + l + 32] = S2[src * 64 + l + 32];
        }
        __syncwarp();
        {
            float2 o[4]; wgemv4(xw, Ws2, l, o);
#pragma unroll
            for (int r = 0; r < 4; ++r) {
                long long row = bb + r;
                float n2 = (row < (long long)N) ? (float)c2[row] : 0.f;
                acc[r].x += o[r].x + n2 * b2l;
                acc[r].y += o[r].y + n2 * b2h;
            }
        }
        __syncwarp();
        // --- S1 @ W1 -> M, then finish P
#pragma unroll
        for (int r = 0; r < 4; ++r) {
            long long row = bb + r;
            long long src = (row < (long long)N) ? row : bb;
            xw[r * 64 + l]      = S1[src * 64 + l];
            xw[r * 64 + l + 32] = S1[src * 64 + l + 32];
        }
        __syncwarp();
        {
            float2 o[4]; wgemv4(xw, Ws1, l, o);
#pragma unroll
            for (int r = 0; r < 4; ++r) {
                long long row = bb + r;
                if (row >= (long long)N) break;
                float n1 = (float)c1[row];
                float mx = o[r].x + n1 * b1l;
                float my = o[r].y + n1 * b1h;
                M[row * 64 + l]      = mx;
                M[row * 64 + l + 32] = my;
                float px = acc[r].x + mx + base[row * 64 + l];
                float py = acc[r].y + my + base[row * 64 + l + 32];
                P[row * 64 + l]      = px;
                P[row * 64 + l + 32] = py;
            }
        }
        __syncwarp();
    }
}

// ---------------------------------------------------------------------------
// MLP: out[e] = relu((P[e] + M[inv[e]]) @ W1 + b1) @ W2 + b2
// ---------------------------------------------------------------------------
__global__ __launch_bounds__(256) void mlp_kernel(
    const float* __restrict__ Pin, const float* __restrict__ Min,
    const void* __restrict__ inv,
    const float* __restrict__ W1, const float* __restrict__ b1,
    const float* __restrict__ W2, const float* __restrict__ b2,
    float* __restrict__ out, int N)
{
    __shared__ float2 Ws1[2048];
    __shared__ float2 Ws2[2048];
    __shared__ float  bsh[128];
    __shared__ float  xbuf[8 * 256];

    int tid = threadIdx.x;
    for (int i = tid; i < 2048; i += blockDim.x) {
        int kp = i >> 6, j = i & 63;
        Ws1[i] = make_float2(W1[(2 * kp) * 64 + j], W1[(2 * kp + 1) * 64 + j]);
        Ws2[i] = make_float2(W2[(2 * kp) * 64 + j], W2[(2 * kp + 1) * 64 + j]);
    }
    for (int i = tid; i < 64; i += blockDim.x) { bsh[i] = b1[i]; bsh[64 + i] = b2[i]; }
    __syncthreads();

    int is64 = g_is64;
    int wid = tid >> 5, l = tid & 31;
    float* xw = xbuf + wid * 256;
    float b1l = bsh[l], b1h = bsh[l + 32];
    float b2l = bsh[64 + l], b2h = bsh[96 + l];

    long long gw   = (long long)blockIdx.x * (blockDim.x >> 5) + wid;
    long long totW = (long long)gridDim.x * (blockDim.x >> 5);

    for (long long bb = gw * 4; bb < (long long)N; bb += totW * 4) {
#pragma unroll
        for (int r = 0; r < 4; ++r) {
            long long row = bb + r;
            long long src = (row < (long long)N) ? row : bb;
            long long iv = ldidx(inv, src, is64);
            xw[r * 64 + l]      = Pin[src * 64 + l]      + Min[iv * 64 + l];
            xw[r * 64 + l + 32] = Pin[src * 64 + l + 32] + Min[iv * 64 + l + 32];
        }
        __syncwarp();
        float2 oh[4]; wgemv4(xw, Ws1, l, oh);
        __syncwarp();
#pragma unroll
        for (int r = 0; r < 4; ++r) {
            xw[r * 64 + l]      = fmaxf(oh[r].x + b1l, 0.f);
            xw[r * 64 + l + 32] = fmaxf(oh[r].y + b1h, 0.f);
        }
        __syncwarp();
        float2 oo[4]; wgemv4(xw, Ws2, l, oo);
#pragma unroll
        for (int r = 0; r < 4; ++r) {
            long long row = bb + r;
            if (row >= (long long)N) break;
            out[row * 64 + l]      = oo[r].x + b2l;
            out[row * 64 + l + 32] = oo[r].y + b2h;
        }
        __syncwarp();
    }
}

// ---------------------------------------------------------------------------
// Launch
// ---------------------------------------------------------------------------
extern "C" void kernel_launch(void* const* d_in, const int* in_sizes, int n_in,
                              void* d_out, int out_size)
{
    const float* edge_attr  = (const float*)d_in[0];
    const float* edge_attr2 = (const float*)d_in[1];
    const float* Wp  = (const float*)d_in[2];
    const float* bp  = (const float*)d_in[3];
    const float* W1a = (const float*)d_in[4];
    const float* b1a = (const float*)d_in[5];
    const float* W2a = (const float*)d_in[6];
    const float* b2a = (const float*)d_in[7];
    const float* W1b = (const float*)d_in[8];
    const float* b1b = (const float*)d_in[9];
    const float* W2b = (const float*)d_in[10];
    const float* b2b = (const float*)d_in[11];
    const void* t111 = d_in[12];
    const void* t112 = d_in[13];
    const void* t122 = d_in[14];
    const void* t222 = d_in[15];
    const void* inv1 = d_in[16];
    const void* inv2 = d_in[17];

    int E  = in_sizes[0] / 64;
    int E2 = in_sizes[1] / 64;
    long long T = in_sizes[12] / 3;

    float *S0, *S1, *S2, *M, *P;
    int *c0, *c1, *c2;
    cudaGetSymbolAddress((void**)&S0, g_S0);
    cudaGetSymbolAddress((void**)&S1, g_S1);
    cudaGetSymbolAddress((void**)&S2, g_S2);
    cudaGetSymbolAddress((void**)&M,  g_M);
    cudaGetSymbolAddress((void**)&P,  g_P);
    cudaGetSymbolAddress((void**)&c0, g_c0);
    cudaGetSymbolAddress((void**)&c1, g_c1);
    cudaGetSymbolAddress((void**)&c2, g_c2);

    cudaFuncSetAttribute(combine_kernel,
                         cudaFuncAttributeMaxDynamicSharedMemorySize, COMB_SMEM);

    float* out1 = (float*)d_out;
    float* out2 = out1 + (size_t)E * 64;

    detect_kernel<<<1, 32>>>((const int*)t111);

    int sb = (int)((T * 16 + 255) / 256);
    const int G = 1024;

    // ---- Phase 1 ----
    cudaMemsetAsync(S0, 0, (size_t)E * 64 * sizeof(float));
    cudaMemsetAsync(S1, 0, (size_t)E * 64 * sizeof(float));
    cudaMemsetAsync(S2, 0, (size_t)E * 64 * sizeof(float));
    cudaMemsetAsync(c0, 0, (size_t)E * sizeof(int));
    cudaMemsetAsync(c1, 0, (size_t)E * sizeof(int));
    cudaMemsetAsync(c2, 0, (size_t)E * sizeof(int));

    // m111: gather ik(row1)+kj(row2) of edge_attr, scatter to ij(row0)
    scatter_kernel<<<sb, 256>>>(t111, 0, T, 2 * T, edge_attr, edge_attr, S0, c0, (int)T);
    // m112: edge_attr[ik] + edge_attr2[kj] -> ij
    scatter_kernel<<<sb, 256>>>(t112, 0, T, 2 * T, edge_attr, edge_attr2, S1, c1, (int)T);
    // m122: edge_attr2[ik] + edge_attr2[kj] -> ij
    scatter_kernel<<<sb, 256>>>(t122, 0, T, 2 * T, edge_attr2, edge_attr2, S2, c2, (int)T);

    combine_kernel<<<G, 256, COMB_SMEM>>>(S0, S1, S2, c0, c1, c2,
                                          Wp, bp, 0, edge_attr, M, P, E);
    mlp_kernel<<<G, 256>>>(P, M, inv1, W1a, b1a, W2a, b2a, out1, E);

    // ---- Phase 2 ----
    cudaMemsetAsync(S0, 0, (size_t)E2 * 64 * sizeof(float));
    cudaMemsetAsync(S1, 0, (size_t)E2 * 64 * sizeof(float));
    cudaMemsetAsync(S2, 0, (size_t)E2 * 64 * sizeof(float));
    cudaMemsetAsync(c0, 0, (size_t)E2 * sizeof(int));
    cudaMemsetAsync(c1, 0, (size_t)E2 * sizeof(int));
    cudaMemsetAsync(c2, 0, (size_t)E2 * sizeof(int));

    // m211: new_edge_attr[ij(row0)] + new_edge_attr[ik(row1)] -> kj(row2)
    scatter_kernel<<<sb, 256>>>(t112, 2 * T, 0, T, out1, out1, S0, c0, (int)T);
    // m212: new_edge_attr[ij(row0)] + edge_attr2[kj(row2)] -> ik(row1)
    scatter_kernel<<<sb, 256>>>(t122, T, 0, 2 * T, out1, edge_attr2, S1, c1, (int)T);
    // m222: edge_attr2[ik(row1)] + edge_attr2[kj(row2)] -> ij(row0)
    scatter_kernel<<<sb, 256>>>(t222, 0, T, 2 * T, edge_attr2, edge_attr2, S2, c2, (int)T);

    combine_kernel<<<G, 256, COMB_SMEM>>>(S0, S1, S2, c0, c1, c2,
                                          Wp, bp, 3, edge_attr2, M, P, E2);
    mlp_kernel<<<G, 256>>>(P, M, inv2, W1b, b1b, W2b, b2b, out2, E2);
}

// round 3
// speedup vs baseline: 1.4209x; 1.4209x over previous
#include <cuda_runtime.h>
#include <cuda_bf16.h>
#include <cstdint>
#include <cstddef>

#define MAX_E2 1000000

// ---------------------------------------------------------------------------
// Scratch
// ---------------------------------------------------------------------------
__device__ float g_S0[(size_t)MAX_E2 * 64];
__device__ float g_S1[(size_t)MAX_E2 * 64];
__device__ float g_S2[(size_t)MAX_E2 * 64];
__device__ float g_M [(size_t)MAX_E2 * 64];
__device__ float g_P [(size_t)MAX_E2 * 64];
__device__ int   g_c0[MAX_E2];
__device__ int   g_c1[MAX_E2];
__device__ int   g_c2[MAX_E2];
__device__ int   g_is64;
// 10 weights (6 proj + W1a,W2a,W1b,W2b): hi[64x64] + lo[64x64] bf16, stored
// transposed (row n, col k). [w*8192 + hl*4096 + n*64 + k]
__device__ __nv_bfloat16 g_Wb[10 * 2 * 4096];

// ---------------------------------------------------------------------------
// Helpers
// ---------------------------------------------------------------------------
__device__ __forceinline__ uint32_t smem_u32(const void* p) {
    uint32_t a;
    asm("{ .reg .u64 t; cvta.to.shared.u64 t, %1; cvt.u32.u64 %0, t; }" : "=r"(a) : "l"(p));
    return a;
}

__device__ __forceinline__ long long ldidx(const void* b, long long i, int is64) {
    if (is64) return ((const long long*)b)[i];
    return (long long)((const int*)b)[i];
}

__device__ __forceinline__ void ldsm4(uint32_t* r, uint32_t addr) {
    asm volatile("ldmatrix.sync.aligned.m8n8.x4.shared.b16 {%0,%1,%2,%3}, [%4];"
                 : "=r"(r[0]), "=r"(r[1]), "=r"(r[2]), "=r"(r[3]) : "r"(addr));
}

__device__ __forceinline__ void mma16816(float* d, const uint32_t* a, const uint32_t* b) {
    asm volatile("mma.sync.aligned.m16n8k16.row.col.f32.bf16.bf16.f32 "
                 "{%0,%1,%2,%3}, {%4,%5,%6,%7}, {%8,%9}, {%0,%1,%2,%3};"
                 : "+f"(d[0]), "+f"(d[1]), "+f"(d[2]), "+f"(d[3])
                 : "r"(a[0]), "r"(a[1]), "r"(a[2]), "r"(a[3]), "r"(b[0]), "r"(b[1]));
}

__device__ __forceinline__ void split_pack8(const float* x, uint4& vh, uint4& vl) {
    unsigned short hs[8], ls[8];
#pragma unroll
    for (int i = 0; i < 8; ++i) {
        __nv_bfloat16 h = __float2bfloat16_rn(x[i]);
        float r = x[i] - __bfloat162float(h);
        hs[i] = __bfloat16_as_ushort(h);
        ls[i] = __bfloat16_as_ushort(__float2bfloat16_rn(r));
    }
    vh.x = hs[0] | ((uint32_t)hs[1] << 16); vh.y = hs[2] | ((uint32_t)hs[3] << 16);
    vh.z = hs[4] | ((uint32_t)hs[5] << 16); vh.w = hs[6] | ((uint32_t)hs[7] << 16);
    vl.x = ls[0] | ((uint32_t)ls[1] << 16); vl.y = ls[2] | ((uint32_t)ls[3] << 16);
    vl.z = ls[4] | ((uint32_t)ls[5] << 16); vl.w = ls[6] | ((uint32_t)ls[7] << 16);
}

__device__ __forceinline__ void split2(float x0, float x1, uint32_t& h, uint32_t& lo) {
    __nv_bfloat16 h0 = __float2bfloat16_rn(x0);
    __nv_bfloat16 h1 = __float2bfloat16_rn(x1);
    float r0 = x0 - __bfloat162float(h0);
    float r1 = x1 - __bfloat162float(h1);
    h  = (uint32_t)__bfloat16_as_ushort(h0) | ((uint32_t)__bfloat16_as_ushort(h1) << 16);
    lo = (uint32_t)__bfloat16_as_ushort(__float2bfloat16_rn(r0))
       | ((uint32_t)__bfloat16_as_ushort(__float2bfloat16_rn(r1)) << 16);
}

// ---------------------------------------------------------------------------
// Index dtype detect
// ---------------------------------------------------------------------------
__global__ void detect_kernel(const int* __restrict__ p) {
    if (threadIdx.x == 0 && blockIdx.x == 0) {
        int acc = 0;
#pragma unroll 1
        for (int i = 0; i < 128; ++i) acc |= p[2 * i + 1];
        g_is64 = (acc == 0) ? 1 : 0;
    }
}

// ---------------------------------------------------------------------------
// Weight prep: transpose + bf16 hi/lo split
// ---------------------------------------------------------------------------
__global__ void prep_kernel(const float* __restrict__ Wp,
                            const float* __restrict__ W1a, const float* __restrict__ W2a,
                            const float* __restrict__ W1b, const float* __restrict__ W2b) {
    int w = blockIdx.x;
    const float* src;
    if (w < 6) src = Wp + (size_t)w * 4096;
    else if (w == 6) src = W1a;
    else if (w == 7) src = W2a;
    else if (w == 8) src = W1b;
    else src = W2b;
    __nv_bfloat16* dh = g_Wb + (size_t)w * 8192;
    __nv_bfloat16* dl = dh + 4096;
    for (int idx = threadIdx.x; idx < 4096; idx += blockDim.x) {
        int n = idx >> 6, k = idx & 63;
        float x = src[k * 64 + n];
        __nv_bfloat16 h = __float2bfloat16_rn(x);
        dh[idx] = h;
        dl[idx] = __float2bfloat16_rn(x - __bfloat162float(h));
    }
}

// ---------------------------------------------------------------------------
// Scatter (near DRAM roofline, unchanged)
// ---------------------------------------------------------------------------
__global__ __launch_bounds__(256) void scatter_kernel(
    const void* __restrict__ tri,
    long long offS, long long offA, long long offB,
    const float* __restrict__ srcA, const float* __restrict__ srcB,
    float* __restrict__ S, int* __restrict__ cnt, int T)
{
    long long g = (long long)blockIdx.x * blockDim.x + threadIdx.x;
    long long t = g >> 4;
    int c = (int)(g & 15);
    if (t >= (long long)T) return;
    int is64 = g_is64;
    long long s = ldidx(tri, offS + t, is64);
    long long a = ldidx(tri, offA + t, is64);
    long long b = ldidx(tri, offB + t, is64);
    float4 va = __ldg((const float4*)(srcA + a * 64) + c);
    float4 vb = __ldg((const float4*)(srcB + b * 64) + c);
    float4 v = make_float4(va.x + vb.x, va.y + vb.y, va.z + vb.z, va.w + vb.w);
    float* dst = S + s * 64 + c * 4;
    asm volatile("red.global.add.v4.f32 [%0], {%1,%2,%3,%4};"
                 :: "l"(dst), "f"(v.x), "f"(v.y), "f"(v.z), "f"(v.w) : "memory");
    if (c == 0) atomicAdd(cnt + s, 1);
}

// ---------------------------------------------------------------------------
// Shared-memory layouts (byte offsets). A rows padded to 72 bf16 = 144B
// (conflict-free ldmatrix). A: 128 rows hi + 128 rows lo.
// ---------------------------------------------------------------------------
#define A_HI 0
#define A_LO 18432
#define A_END 36864
// combine: 3 weights x (hi,lo), each 64 x 144B
#define CB_B(w, hl) (A_END + (w) * 18432 + (hl) * 9216)
#define CB_BIAS (A_END + 3 * 18432)
#define CB_SMEM (CB_BIAS + 192 * 4)
// mlp: 2 weights
#define ML_B(w, hl) (A_END + (w) * 18432 + (hl) * 9216)
#define ML_BIAS (A_END + 2 * 18432)
#define ML_SMEM (ML_BIAS + 128 * 4)

// GEMM over one warp-private 16-row slab: acc[8][4] += A(16x64) @ B(64x64)
__device__ __forceinline__ void slab_gemm(uint32_t aAddr, uint32_t bBaseH,
                                          uint32_t bLaneOff, float acc[8][4]) {
#pragma unroll
    for (int kk = 0; kk < 4; ++kk) {
        uint32_t Ah[4], Al[4];
        ldsm4(Ah, aAddr + kk * 32);
        ldsm4(Al, aAddr + kk * 32 + A_LO);
#pragma unroll
        for (int p = 0; p < 4; ++p) {
            uint32_t BH[4], BL[4];
            uint32_t ba = bBaseH + p * 16 * 144 + kk * 32 + bLaneOff;
            ldsm4(BH, ba);
            ldsm4(BL, ba + 9216);
            mma16816(acc[2 * p],     Ah, BH);
            mma16816(acc[2 * p],     Ah, BL);
            mma16816(acc[2 * p],     Al, BH);
            mma16816(acc[2 * p + 1], Ah, BH + 2);
            mma16816(acc[2 * p + 1], Ah, BL + 2);
            mma16816(acc[2 * p + 1], Al, BH + 2);
        }
    }
}

// ---------------------------------------------------------------------------
// Combine: acc = S1@W1 (write M = acc + c1*b1), then += S0@W0 + S2@W2,
// P = acc + base + c0*b0 + c1*b1 + c2*b2
// ---------------------------------------------------------------------------
__global__ __launch_bounds__(256) void combine_mma(
    const float* __restrict__ S0, const float* __restrict__ S1, const float* __restrict__ S2,
    const int* __restrict__ c0, const int* __restrict__ c1, const int* __restrict__ c2,
    int wb, const float* __restrict__ bp,
    const float* __restrict__ base, float* __restrict__ M, float* __restrict__ P,
    long long N)
{
    extern __shared__ char smem[];
    uint32_t sb = smem_u32(smem);
    int tid = threadIdx.x, wid = tid >> 5, l = tid & 31;
    float* bias_s = (float*)(smem + CB_BIAS);

    const int wsel[3] = {1, 0, 2};  // phase order: S1, S0, S2
    // stage 3 weights (hi/lo) into padded smem
    for (int i = tid; i < 3072; i += 256) {
        int w = i >> 10, hl = (i >> 9) & 1, r = (i >> 3) & 63, c = i & 7;
        const uint4* s = (const uint4*)(g_Wb + (size_t)(wb + wsel[w]) * 8192 + hl * 4096);
        *(uint4*)(smem + CB_B(w, hl) + r * 144 + c * 16) = s[r * 8 + c];
    }
    for (int i = tid; i < 192; i += 256) bias_s[i] = bp[wb * 64 + i];
    __syncthreads();

    long long tile0 = (long long)blockIdx.x * 128;
    int slab = wid * 16;
    int g = l >> 2;
    long long row0 = tile0 + slab + g, row1 = row0 + 8;
    bool ok0 = row0 < N, ok1 = row1 < N;

    uint32_t aAddr = sb + A_HI + (uint32_t)(slab + (l & 15)) * 144 + ((l >> 4) * 16);
    uint32_t bLaneOff = (uint32_t)((((l >> 4) & 1) * 8 + (l & 7)) * 144 + ((l >> 3) & 1) * 16);

    float acc[8][4];
#pragma unroll
    for (int i = 0; i < 8; ++i)
#pragma unroll
        for (int j = 0; j < 4; ++j) acc[i][j] = 0.f;

    float cb1_0 = ok0 ? (float)__ldg(c1 + row0) : 0.f;
    float cb1_1 = ok1 ? (float)__ldg(c1 + row1) : 0.f;

    const float* srcs[3] = {S1, S0, S2};
#pragma unroll 1
    for (int ph = 0; ph < 3; ++ph) {
        __syncwarp();
        // stage this warp's 16 rows of A (fp32 -> bf16 hi/lo)
        const float4* src4 = (const float4*)srcs[ph];
#pragma unroll
        for (int it = 0; it < 4; ++it) {
            int chunk = it * 32 + l;
            int r = chunk >> 3, c = chunk & 7;
            long long row = tile0 + slab + r;
            float xs[8] = {0, 0, 0, 0, 0, 0, 0, 0};
            if (row < N) {
                float4 x0 = __ldg(src4 + row * 16 + c * 2);
                float4 x1 = __ldg(src4 + row * 16 + c * 2 + 1);
                xs[0] = x0.x; xs[1] = x0.y; xs[2] = x0.z; xs[3] = x0.w;
                xs[4] = x1.x; xs[5] = x1.y; xs[6] = x1.z; xs[7] = x1.w;
            }
            uint4 vh, vl; split_pack8(xs, vh, vl);
            *(uint4*)(smem + A_HI + (slab + r) * 144 + c * 16) = vh;
            *(uint4*)(smem + A_LO + (slab + r) * 144 + c * 16) = vl;
        }
        __syncwarp();
        slab_gemm(aAddr, sb + CB_B(ph, 0), bLaneOff, acc);

        if (ph == 0) {
            // write M = acc + c1*b1
#pragma unroll
            for (int nt = 0; nt < 8; ++nt) {
                int col = nt * 8 + 2 * (l & 3);
                float bx = bias_s[64 + col], by = bias_s[64 + col + 1];
                if (ok0) *(float2*)(M + row0 * 64 + col) =
                    make_float2(acc[nt][0] + cb1_0 * bx, acc[nt][1] + cb1_0 * by);
                if (ok1) *(float2*)(M + row1 * 64 + col) =
                    make_float2(acc[nt][2] + cb1_1 * bx, acc[nt][3] + cb1_1 * by);
            }
        }
    }

    float cb0_0 = ok0 ? (float)__ldg(c0 + row0) : 0.f;
    float cb0_1 = ok1 ? (float)__ldg(c0 + row1) : 0.f;
    float cb2_0 = ok0 ? (float)__ldg(c2 + row0) : 0.f;
    float cb2_1 = ok1 ? (float)__ldg(c2 + row1) : 0.f;
#pragma unroll
    for (int nt = 0; nt < 8; ++nt) {
        int col = nt * 8 + 2 * (l & 3);
        float b0x = bias_s[col],       b0y = bias_s[col + 1];
        float b1x = bias_s[64 + col],  b1y = bias_s[64 + col + 1];
        float b2x = bias_s[128 + col], b2y = bias_s[128 + col + 1];
        if (ok0) {
            float2 bs = *(const float2*)(base + row0 * 64 + col);
            *(float2*)(P + row0 * 64 + col) = make_float2(
                acc[nt][0] + bs.x + cb0_0 * b0x + cb1_0 * b1x + cb2_0 * b2x,
                acc[nt][1] + bs.y + cb0_0 * b0y + cb1_0 * b1y + cb2_0 * b2y);
        }
        if (ok1) {
            float2 bs = *(const float2*)(base + row1 * 64 + col);
            *(float2*)(P + row1 * 64 + col) = make_float2(
                acc[nt][2] + bs.x + cb0_1 * b0x + cb1_1 * b1x + cb2_1 * b2x,
                acc[nt][3] + bs.y + cb0_1 * b0y + cb1_1 * b1y + cb2_1 * b2y);
        }
    }
}

// ---------------------------------------------------------------------------
// MLP: X = P + M[inv]; H = relu(X@W1 + b1); out = H@W2 + b2
// ---------------------------------------------------------------------------
__global__ __launch_bounds__(256) void mlp_mma(
    const float* __restrict__ Pin, const float* __restrict__ Min,
    const void* __restrict__ inv,
    int w1id, int w2id,
    const float* __restrict__ b1, const float* __restrict__ b2,
    float* __restrict__ out, long long N)
{
    extern __shared__ char smem[];
    uint32_t sb = smem_u32(smem);
    int tid = threadIdx.x, wid = tid >> 5, l = tid & 31;
    float* bias_s = (float*)(smem + ML_BIAS);
    int is64 = g_is64;

    int wids[2] = {w1id, w2id};
    for (int i = tid; i < 2048; i += 256) {
        int w = i >> 10, hl = (i >> 9) & 1, r = (i >> 3) & 63, c = i & 7;
        const uint4* s = (const uint4*)(g_Wb + (size_t)wids[w] * 8192 + hl * 4096);
        *(uint4*)(smem + ML_B(w, hl) + r * 144 + c * 16) = s[r * 8 + c];
    }
    for (int i = tid; i < 64; i += 256) { bias_s[i] = b1[i]; bias_s[64 + i] = b2[i]; }
    __syncthreads();

    long long tile0 = (long long)blockIdx.x * 128;
    int slab = wid * 16;
    int g = l >> 2;
    long long row0 = tile0 + slab + g, row1 = row0 + 8;
    bool ok0 = row0 < N, ok1 = row1 < N;

    uint32_t aAddr = sb + A_HI + (uint32_t)(slab + (l & 15)) * 144 + ((l >> 4) * 16);
    uint32_t bLaneOff = (uint32_t)((((l >> 4) & 1) * 8 + (l & 7)) * 144 + ((l >> 3) & 1) * 16);

    // stage X = P[row] + M[inv[row]]
    const float4* p4 = (const float4*)Pin;
    const float4* m4 = (const float4*)Min;
#pragma unroll
    for (int it = 0; it < 4; ++it) {
        int chunk = it * 32 + l;
        int r = chunk >> 3, c = chunk & 7;
        long long row = tile0 + slab + r;
        float xs[8] = {0, 0, 0, 0, 0, 0, 0, 0};
        if (row < N) {
            long long iv = ldidx(inv, row, is64);
            float4 a0 = __ldg(p4 + row * 16 + c * 2);
            float4 a1 = __ldg(p4 + row * 16 + c * 2 + 1);
            float4 q0 = __ldg(m4 + iv * 16 + c * 2);
            float4 q1 = __ldg(m4 + iv * 16 + c * 2 + 1);
            xs[0] = a0.x + q0.x; xs[1] = a0.y + q0.y; xs[2] = a0.z + q0.z; xs[3] = a0.w + q0.w;
            xs[4] = a1.x + q1.x; xs[5] = a1.y + q1.y; xs[6] = a1.z + q1.z; xs[7] = a1.w + q1.w;
        }
        uint4 vh, vl; split_pack8(xs, vh, vl);
        *(uint4*)(smem + A_HI + (slab + r) * 144 + c * 16) = vh;
        *(uint4*)(smem + A_LO + (slab + r) * 144 + c * 16) = vl;
    }
    __syncwarp();

    float acc[8][4];
#pragma unroll
    for (int i = 0; i < 8; ++i)
#pragma unroll
        for (int j = 0; j < 4; ++j) acc[i][j] = 0.f;
    slab_gemm(aAddr, sb + ML_B(0, 0), bLaneOff, acc);

    // H = relu(acc + b1) -> restage (warp-private rows) as bf16 hi/lo
    __syncwarp();
#pragma unroll
    for (int nt = 0; nt < 8; ++nt) {
        int col = nt * 8 + 2 * (l & 3);
        float bx = bias_s[col], by = bias_s[col + 1];
        float h0 = fmaxf(acc[nt][0] + bx, 0.f);
        float h1 = fmaxf(acc[nt][1] + by, 0.f);
        float h2 = fmaxf(acc[nt][2] + bx, 0.f);
        float h3 = fmaxf(acc[nt][3] + by, 0.f);
        uint32_t vh, vl;
        split2(h0, h1, vh, vl);
        *(uint32_t*)(smem + A_HI + (slab + g) * 144 + col * 2) = vh;
        *(uint32_t*)(smem + A_LO + (slab + g) * 144 + col * 2) = vl;
        split2(h2, h3, vh, vl);
        *(uint32_t*)(smem + A_HI + (slab + g + 8) * 144 + col * 2) = vh;
        *(uint32_t*)(smem + A_LO + (slab + g + 8) * 144 + col * 2) = vl;
    }
    __syncwarp();

#pragma unroll
    for (int i = 0; i < 8; ++i)
#pragma unroll
        for (int j = 0; j < 4; ++j) acc[i][j] = 0.f;
    slab_gemm(aAddr, sb + ML_B(1, 0), bLaneOff, acc);

#pragma unroll
    for (int nt = 0; nt < 8; ++nt) {
        int col = nt * 8 + 2 * (l & 3);
        float bx = bias_s[64 + col], by = bias_s[64 + col + 1];
        if (ok0) *(float2*)(out + row0 * 64 + col) =
            make_float2(acc[nt][0] + bx, acc[nt][1] + by);
        if (ok1) *(float2*)(out + row1 * 64 + col) =
            make_float2(acc[nt][2] + bx, acc[nt][3] + by);
    }
}

// ---------------------------------------------------------------------------
// Launch
// ---------------------------------------------------------------------------
extern "C" void kernel_launch(void* const* d_in, const int* in_sizes, int n_in,
                              void* d_out, int out_size)
{
    const float* edge_attr  = (const float*)d_in[0];
    const float* edge_attr2 = (const float*)d_in[1];
    const float* Wp  = (const float*)d_in[2];
    const float* bp  = (const float*)d_in[3];
    const float* W1a = (const float*)d_in[4];
    const float* b1a = (const float*)d_in[5];
    const float* W2a = (const float*)d_in[6];
    const float* b2a = (const float*)d_in[7];
    const float* W1b = (const float*)d_in[8];
    const float* b1b = (const float*)d_in[9];
    const float* W2b = (const float*)d_in[10];
    const float* b2b = (const float*)d_in[11];
    const void* t111 = d_in[12];
    const void* t112 = d_in[13];
    const void* t122 = d_in[14];
    const void* t222 = d_in[15];
    const void* inv1 = d_in[16];
    const void* inv2 = d_in[17];

    int E  = in_sizes[0] / 64;
    int E2 = in_sizes[1] / 64;
    long long T = in_sizes[12] / 3;

    float *S0, *S1, *S2, *M, *P;
    int *c0, *c1, *c2;
    cudaGetSymbolAddress((void**)&S0, g_S0);
    cudaGetSymbolAddress((void**)&S1, g_S1);
    cudaGetSymbolAddress((void**)&S2, g_S2);
    cudaGetSymbolAddress((void**)&M,  g_M);
    cudaGetSymbolAddress((void**)&P,  g_P);
    cudaGetSymbolAddress((void**)&c0, g_c0);
    cudaGetSymbolAddress((void**)&c1, g_c1);
    cudaGetSymbolAddress((void**)&c2, g_c2);

    cudaFuncSetAttribute(combine_mma, cudaFuncAttributeMaxDynamicSharedMemorySize, CB_SMEM);
    cudaFuncSetAttribute(mlp_mma,     cudaFuncAttributeMaxDynamicSharedMemorySize, ML_SMEM);

    float* out1 = (float*)d_out;
    float* out2 = out1 + (size_t)E * 64;

    detect_kernel<<<1, 32>>>((const int*)t111);
    prep_kernel<<<10, 256>>>(Wp, W1a, W2a, W1b, W2b);

    int sb = (int)((T * 16 + 255) / 256);
    int tiles1 = (E  + 127) / 128;
    int tiles2 = (E2 + 127) / 128;

    // ---- Phase 1 ----
    cudaMemsetAsync(S0, 0, (size_t)E * 64 * sizeof(float));
    cudaMemsetAsync(S1, 0, (size_t)E * 64 * sizeof(float));
    cudaMemsetAsync(S2, 0, (size_t)E * 64 * sizeof(float));
    cudaMemsetAsync(c0, 0, (size_t)E * sizeof(int));
    cudaMemsetAsync(c1, 0, (size_t)E * sizeof(int));
    cudaMemsetAsync(c2, 0, (size_t)E * sizeof(int));

    scatter_kernel<<<sb, 256>>>(t111, 0, T, 2 * T, edge_attr, edge_attr, S0, c0, (int)T);
    scatter_kernel<<<sb, 256>>>(t112, 0, T, 2 * T, edge_attr, edge_attr2, S1, c1, (int)T);
    scatter_kernel<<<sb, 256>>>(t122, 0, T, 2 * T, edge_attr2, edge_attr2, S2, c2, (int)T);

    combine_mma<<<tiles1, 256, CB_SMEM>>>(S0, S1, S2, c0, c1, c2, 0, bp,
                                          edge_attr, M, P, (long long)E);
    mlp_mma<<<tiles1, 256, ML_SMEM>>>(P, M, inv1, 6, 7, b1a, b2a, out1, (long long)E);

    // ---- Phase 2 ----
    cudaMemsetAsync(S0, 0, (size_t)E2 * 64 * sizeof(float));
    cudaMemsetAsync(S1, 0, (size_t)E2 * 64 * sizeof(float));
    cudaMemsetAsync(S2, 0, (size_t)E2 * 64 * sizeof(float));
    cudaMemsetAsync(c0, 0, (size_t)E2 * sizeof(int));
    cudaMemsetAsync(c1, 0, (size_t)E2 * sizeof(int));
    cudaMemsetAsync(c2, 0, (size_t)E2 * sizeof(int));

    scatter_kernel<<<sb, 256>>>(t112, 2 * T, 0, T, out1, out1, S0, c0, (int)T);
    scatter_kernel<<<sb, 256>>>(t122, T, 0, 2 * T, out1, edge_attr2, S1, c1, (int)T);
    scatter_kernel<<<sb, 256>>>(t222, 0, T, 2 * T, edge_attr2, edge_attr2, S2, c2, (int)T);

    combine_mma<<<tiles2, 256, CB_SMEM>>>(S0, S1, S2, c0, c1, c2, 3, bp,
                                          edge_attr2, M, P, (long long)E2);
    mlp_mma<<<tiles2, 256, ML_SMEM>>>(P, M, inv2, 8, 9, b1b, b2b, out2, (long long)E2);
}

// round 4
// speedup vs baseline: 1.6943x; 1.1924x over previous
#include <cuda_runtime.h>
#include <cuda_bf16.h>
#include <cstdint>
#include <cstddef>

#define MAX_E2 1000000

// ---------------------------------------------------------------------------
// Scratch (contiguous: S = 3 segments, c = 3 segments, bases set per phase)
// ---------------------------------------------------------------------------
__device__ float g_S[(size_t)3 * MAX_E2 * 64];
__device__ float g_M[(size_t)MAX_E2 * 64];
__device__ float g_P[(size_t)MAX_E2 * 64];
__device__ int   g_c[(size_t)3 * MAX_E2];
__device__ int   g_is64;
// 10 weights: hi[64x64] + lo[64x64] bf16, transposed (row n, col k)
__device__ __nv_bfloat16 g_Wb[10 * 2 * 4096];

// ---------------------------------------------------------------------------
// Helpers
// ---------------------------------------------------------------------------
__device__ __forceinline__ uint32_t smem_u32(const void* p) {
    uint32_t a;
    asm("{ .reg .u64 t; cvta.to.shared.u64 t, %1; cvt.u32.u64 %0, t; }" : "=r"(a) : "l"(p));
    return a;
}

__device__ __forceinline__ long long ldidx(const void* b, long long i, int is64) {
    if (is64) return ((const long long*)b)[i];
    return (long long)((const int*)b)[i];
}

__device__ __forceinline__ void ldsm4(uint32_t* r, uint32_t addr) {
    asm volatile("ldmatrix.sync.aligned.m8n8.x4.shared.b16 {%0,%1,%2,%3}, [%4];"
                 : "=r"(r[0]), "=r"(r[1]), "=r"(r[2]), "=r"(r[3]) : "r"(addr));
}

__device__ __forceinline__ void mma16816(float* d, const uint32_t* a, const uint32_t* b) {
    asm volatile("mma.sync.aligned.m16n8k16.row.col.f32.bf16.bf16.f32 "
                 "{%0,%1,%2,%3}, {%4,%5,%6,%7}, {%8,%9}, {%0,%1,%2,%3};"
                 : "+f"(d[0]), "+f"(d[1]), "+f"(d[2]), "+f"(d[3])
                 : "r"(a[0]), "r"(a[1]), "r"(a[2]), "r"(a[3]), "r"(b[0]), "r"(b[1]));
}

__device__ __forceinline__ void split2(float x0, float x1, uint32_t& h, uint32_t& lo) {
    __nv_bfloat16 h0 = __float2bfloat16_rn(x0);
    __nv_bfloat16 h1 = __float2bfloat16_rn(x1);
    float r0 = x0 - __bfloat162float(h0);
    float r1 = x1 - __bfloat162float(h1);
    h  = (uint32_t)__bfloat16_as_ushort(h0) | ((uint32_t)__bfloat16_as_ushort(h1) << 16);
    lo = (uint32_t)__bfloat16_as_ushort(__float2bfloat16_rn(r0))
       | ((uint32_t)__bfloat16_as_ushort(__float2bfloat16_rn(r1)) << 16);
}

// A-fragment direct loads: 16 float2 per thread covering a 16x64 slab.
// a0=[g][k0..k0+1] a1=[g+8][k0..] a2=[g][k0+8..] a3=[g+8][k0+8..], k0=2q+16kk
__device__ __forceinline__ void load16(const float* __restrict__ X,
                                       long long rowA, long long rowB,
                                       bool okA, bool okB, int q, uint2* f) {
    const uint2* pA = (const uint2*)(X + rowA * 64);
    const uint2* pB = (const uint2*)(X + rowB * 64);
    uint2 z = make_uint2(0u, 0u);
#pragma unroll
    for (int kk = 0; kk < 4; ++kk) {
        f[kk * 4 + 0] = okA ? __ldg(pA + kk * 8 + q)     : z;
        f[kk * 4 + 1] = okB ? __ldg(pB + kk * 8 + q)     : z;
        f[kk * 4 + 2] = okA ? __ldg(pA + kk * 8 + 4 + q) : z;
        f[kk * 4 + 3] = okB ? __ldg(pB + kk * 8 + 4 + q) : z;
    }
}

__device__ __forceinline__ void conv16(const uint2* f, uint32_t* Ah, uint32_t* Al) {
#pragma unroll
    for (int i = 0; i < 16; ++i)
        split2(__uint_as_float(f[i].x), __uint_as_float(f[i].y), Ah[i], Al[i]);
}

// GEMM: acc[8][4] += slab(16x64, frags Ah/Al) @ B(64x64, smem hi at bBaseH, lo +9216)
__device__ __forceinline__ void frag_gemm(const uint32_t* Ah, const uint32_t* Al,
                                          uint32_t bBaseH, uint32_t bLaneOff,
                                          float acc[8][4]) {
#pragma unroll
    for (int kk = 0; kk < 4; ++kk) {
        const uint32_t* ah = Ah + kk * 4;
        const uint32_t* al = Al + kk * 4;
#pragma unroll
        for (int p = 0; p < 4; ++p) {
            uint32_t BH[4], BL[4];
            uint32_t ba = bBaseH + p * 16 * 144 + kk * 32 + bLaneOff;
            ldsm4(BH, ba);
            ldsm4(BL, ba + 9216);
            mma16816(acc[2 * p],     ah, BH);
            mma16816(acc[2 * p],     ah, BL);
            mma16816(acc[2 * p],     al, BH);
            mma16816(acc[2 * p + 1], ah, BH + 2);
            mma16816(acc[2 * p + 1], ah, BL + 2);
            mma16816(acc[2 * p + 1], al, BH + 2);
        }
    }
}

// ---------------------------------------------------------------------------
// Index dtype detect
// ---------------------------------------------------------------------------
__global__ void detect_kernel(const int* __restrict__ p) {
    if (threadIdx.x == 0 && blockIdx.x == 0) {
        int acc = 0;
#pragma unroll 1
        for (int i = 0; i < 128; ++i) acc |= p[2 * i + 1];
        g_is64 = (acc == 0) ? 1 : 0;
    }
}

// ---------------------------------------------------------------------------
// Weight prep
// ---------------------------------------------------------------------------
__global__ void prep_kernel(const float* __restrict__ Wp,
                            const float* __restrict__ W1a, const float* __restrict__ W2a,
                            const float* __restrict__ W1b, const float* __restrict__ W2b) {
    int w = blockIdx.x;
    const float* src;
    if (w < 6) src = Wp + (size_t)w * 4096;
    else if (w == 6) src = W1a;
    else if (w == 7) src = W2a;
    else if (w == 8) src = W1b;
    else src = W2b;
    __nv_bfloat16* dh = g_Wb + (size_t)w * 8192;
    __nv_bfloat16* dl = dh + 4096;
    for (int idx = threadIdx.x; idx < 4096; idx += blockDim.x) {
        int n = idx >> 6, k = idx & 63;
        float x = src[k * 64 + n];
        __nv_bfloat16 h = __float2bfloat16_rn(x);
        dh[idx] = h;
        dl[idx] = __float2bfloat16_rn(x - __bfloat162float(h));
    }
}

// ---------------------------------------------------------------------------
// Scatter (unchanged)
// ---------------------------------------------------------------------------
__global__ __launch_bounds__(256) void scatter_kernel(
    const void* __restrict__ tri,
    long long offS, long long offA, long long offB,
    const float* __restrict__ srcA, const float* __restrict__ srcB,
    float* __restrict__ S, int* __restrict__ cnt, int T)
{
    long long g = (long long)blockIdx.x * blockDim.x + threadIdx.x;
    long long t = g >> 4;
    int c = (int)(g & 15);
    if (t >= (long long)T) return;
    int is64 = g_is64;
    long long s = ldidx(tri, offS + t, is64);
    long long a = ldidx(tri, offA + t, is64);
    long long b = ldidx(tri, offB + t, is64);
    float4 va = __ldg((const float4*)(srcA + a * 64) + c);
    float4 vb = __ldg((const float4*)(srcB + b * 64) + c);
    float4 v = make_float4(va.x + vb.x, va.y + vb.y, va.z + vb.z, va.w + vb.w);
    float* dst = S + s * 64 + c * 4;
    asm volatile("red.global.add.v4.f32 [%0], {%1,%2,%3,%4};"
                 :: "l"(dst), "f"(v.x), "f"(v.y), "f"(v.z), "f"(v.w) : "memory");
    if (c == 0) atomicAdd(cnt + s, 1);
}

// ---------------------------------------------------------------------------
// Shared-memory layouts (weights only; 144B-padded rows for conflict-free ldsm)
// ---------------------------------------------------------------------------
#define B_OFF(w, hl) ((w) * 18432 + (hl) * 9216)
#define CB_BIAS (3 * 18432)
#define CB_SMEM (CB_BIAS + 768)
#define ML_BIAS (2 * 18432)
#define ML_SMEM (ML_BIAS + 512)

// ---------------------------------------------------------------------------
// Combine: acc = S1@W1 (write M = acc + c1*b1), then += S0@W0 + S2@W2,
// P = acc + base + c0*b0 + c1*b1 + c2*b2. Persistent grid-stride over tiles.
// ---------------------------------------------------------------------------
__global__ __launch_bounds__(256) void combine_mma(
    const float* __restrict__ S0, const float* __restrict__ S1, const float* __restrict__ S2,
    const int* __restrict__ c0, const int* __restrict__ c1, const int* __restrict__ c2,
    int wb, const float* __restrict__ bp,
    const float* __restrict__ base, float* __restrict__ M, float* __restrict__ P,
    long long N, int numTiles)
{
    extern __shared__ char smem[];
    uint32_t sb = smem_u32(smem);
    int tid = threadIdx.x, wid = tid >> 5, l = tid & 31;
    int q = l & 3, g = l >> 2;
    float* bias_s = (float*)(smem + CB_BIAS);

    const int wsel[3] = {1, 0, 2};  // phase order: S1, S0, S2
    for (int i = tid; i < 3072; i += 256) {
        int w = i >> 10, hl = (i >> 9) & 1, r = (i >> 3) & 63, c = i & 7;
        const uint4* s = (const uint4*)(g_Wb + (size_t)(wb + wsel[w]) * 8192 + hl * 4096);
        *(uint4*)(smem + B_OFF(w, hl) + r * 144 + c * 16) = s[r * 8 + c];
    }
    for (int i = tid; i < 192; i += 256) bias_s[i] = bp[wb * 64 + i];
    __syncthreads();

    uint32_t bLaneOff = (uint32_t)((((l >> 4) & 1) * 8 + (l & 7)) * 144 + ((l >> 3) & 1) * 16);

    for (int tile = blockIdx.x; tile < numTiles; tile += gridDim.x) {
        long long rowS = (long long)tile * 128 + wid * 16;
        long long row0 = rowS + g, row1 = row0 + 8;
        bool ok0 = row0 < N, ok1 = row1 < N;

        uint2 f1[16], fx[16];
        load16(S1, row0, row1, ok0, ok1, q, f1);
        load16(S0, row0, row1, ok0, ok1, q, fx);
        float cb1_0 = ok0 ? (float)__ldg(c1 + row0) : 0.f;
        float cb1_1 = ok1 ? (float)__ldg(c1 + row1) : 0.f;

        uint32_t Ah[16], Al[16];
        conv16(f1, Ah, Al);
        float acc[8][4];
#pragma unroll
        for (int i = 0; i < 8; ++i)
#pragma unroll
            for (int j = 0; j < 4; ++j) acc[i][j] = 0.f;
        frag_gemm(Ah, Al, sb + B_OFF(0, 0), bLaneOff, acc);

        // M = acc(S1 term) + c1*b1
#pragma unroll
        for (int nt = 0; nt < 8; ++nt) {
            int col = nt * 8 + 2 * q;
            float bx = bias_s[64 + col], by = bias_s[64 + col + 1];
            if (ok0) *(float2*)(M + row0 * 64 + col) =
                make_float2(acc[nt][0] + cb1_0 * bx, acc[nt][1] + cb1_0 * by);
            if (ok1) *(float2*)(M + row1 * 64 + col) =
                make_float2(acc[nt][2] + cb1_1 * bx, acc[nt][3] + cb1_1 * by);
        }

        conv16(fx, Ah, Al);
        load16(S2, row0, row1, ok0, ok1, q, fx);
        float cb0_0 = ok0 ? (float)__ldg(c0 + row0) : 0.f;
        float cb0_1 = ok1 ? (float)__ldg(c0 + row1) : 0.f;
        float cb2_0 = ok0 ? (float)__ldg(c2 + row0) : 0.f;
        float cb2_1 = ok1 ? (float)__ldg(c2 + row1) : 0.f;
        frag_gemm(Ah, Al, sb + B_OFF(1, 0), bLaneOff, acc);

        conv16(fx, Ah, Al);
        frag_gemm(Ah, Al, sb + B_OFF(2, 0), bLaneOff, acc);

#pragma unroll
        for (int nt = 0; nt < 8; ++nt) {
            int col = nt * 8 + 2 * q;
            float b0x = bias_s[col],       b0y = bias_s[col + 1];
            float b1x = bias_s[64 + col],  b1y = bias_s[64 + col + 1];
            float b2x = bias_s[128 + col], b2y = bias_s[128 + col + 1];
            if (ok0) {
                float2 bs = *(const float2*)(base + row0 * 64 + col);
                *(float2*)(P + row0 * 64 + col) = make_float2(
                    acc[nt][0] + bs.x + cb0_0 * b0x + cb1_0 * b1x + cb2_0 * b2x,
                    acc[nt][1] + bs.y + cb0_0 * b0y + cb1_0 * b1y + cb2_0 * b2y);
            }
            if (ok1) {
                float2 bs = *(const float2*)(base + row1 * 64 + col);
                *(float2*)(P + row1 * 64 + col) = make_float2(
                    acc[nt][2] + bs.x + cb0_1 * b0x + cb1_1 * b1x + cb2_1 * b2x,
                    acc[nt][3] + bs.y + cb0_1 * b0y + cb1_1 * b1y + cb2_1 * b2y);
            }
        }
    }
}

// ---------------------------------------------------------------------------
// MLP: X = P + M[inv]; H = relu(X@W1 + b1) (register-resident); out = H@W2 + b2
// ---------------------------------------------------------------------------
__global__ __launch_bounds__(256) void mlp_mma(
    const float* __restrict__ Pin, const float* __restrict__ Min,
    const void* __restrict__ inv,
    int w1id, int w2id,
    const float* __restrict__ b1, const float* __restrict__ b2,
    float* __restrict__ out, long long N, int numTiles)
{
    extern __shared__ char smem[];
    uint32_t sb = smem_u32(smem);
    int tid = threadIdx.x, wid = tid >> 5, l = tid & 31;
    int q = l & 3, g = l >> 2;
    float* bias_s = (float*)(smem + ML_BIAS);
    int is64 = g_is64;

    int wids[2] = {w1id, w2id};
    for (int i = tid; i < 2048; i += 256) {
        int w = i >> 10, hl = (i >> 9) & 1, r = (i >> 3) & 63, c = i & 7;
        const uint4* s = (const uint4*)(g_Wb + (size_t)wids[w] * 8192 + hl * 4096);
        *(uint4*)(smem + B_OFF(w, hl) + r * 144 + c * 16) = s[r * 8 + c];
    }
    for (int i = tid; i < 64; i += 256) { bias_s[i] = b1[i]; bias_s[64 + i] = b2[i]; }
    __syncthreads();

    uint32_t bLaneOff = (uint32_t)((((l >> 4) & 1) * 8 + (l & 7)) * 144 + ((l >> 3) & 1) * 16);

    for (int tile = blockIdx.x; tile < numTiles; tile += gridDim.x) {
        long long rowS = (long long)tile * 128 + wid * 16;
        long long row0 = rowS + g, row1 = row0 + 8;
        bool ok0 = row0 < N, ok1 = row1 < N;
        long long iv0 = ok0 ? ldidx(inv, row0, is64) : 0;
        long long iv1 = ok1 ? ldidx(inv, row1, is64) : 0;

        uint2 fP[16], fM[16];
        load16(Pin, row0, row1, ok0, ok1, q, fP);
        load16(Min, iv0, iv1, ok0, ok1, q, fM);

        uint32_t Ah[16], Al[16];
#pragma unroll
        for (int i = 0; i < 16; ++i)
            split2(__uint_as_float(fP[i].x) + __uint_as_float(fM[i].x),
                   __uint_as_float(fP[i].y) + __uint_as_float(fM[i].y), Ah[i], Al[i]);

        float acc[8][4];
#pragma unroll
        for (int i = 0; i < 8; ++i)
#pragma unroll
            for (int j = 0; j < 4; ++j) acc[i][j] = 0.f;
        frag_gemm(Ah, Al, sb + B_OFF(0, 0), bLaneOff, acc);

        // H = relu(acc + b1) mapped directly to next A fragments (nt = 2kk+h)
#pragma unroll
        for (int kk = 0; kk < 4; ++kk) {
            int c0i = kk * 16 + 2 * q;
            float bx0 = bias_s[c0i], by0 = bias_s[c0i + 1];
            float bx8 = bias_s[c0i + 8], by8 = bias_s[c0i + 9];
            split2(fmaxf(acc[2 * kk][0] + bx0, 0.f), fmaxf(acc[2 * kk][1] + by0, 0.f),
                   Ah[kk * 4 + 0], Al[kk * 4 + 0]);
            split2(fmaxf(acc[2 * kk][2] + bx0, 0.f), fmaxf(acc[2 * kk][3] + by0, 0.f),
                   Ah[kk * 4 + 1], Al[kk * 4 + 1]);
            split2(fmaxf(acc[2 * kk + 1][0] + bx8, 0.f), fmaxf(acc[2 * kk + 1][1] + by8, 0.f),
                   Ah[kk * 4 + 2], Al[kk * 4 + 2]);
            split2(fmaxf(acc[2 * kk + 1][2] + bx8, 0.f), fmaxf(acc[2 * kk + 1][3] + by8, 0.f),
                   Ah[kk * 4 + 3], Al[kk * 4 + 3]);
        }

#pragma unroll
        for (int i = 0; i < 8; ++i)
#pragma unroll
            for (int j = 0; j < 4; ++j) acc[i][j] = 0.f;
        frag_gemm(Ah, Al, sb + B_OFF(1, 0), bLaneOff, acc);

#pragma unroll
        for (int nt = 0; nt < 8; ++nt) {
            int col = nt * 8 + 2 * q;
            float bx = bias_s[64 + col], by = bias_s[64 + col + 1];
            if (ok0) *(float2*)(out + row0 * 64 + col) =
                make_float2(acc[nt][0] + bx, acc[nt][1] + by);
            if (ok1) *(float2*)(out + row1 * 64 + col) =
                make_float2(acc[nt][2] + bx, acc[nt][3] + by);
        }
    }
}

// ---------------------------------------------------------------------------
// Launch
// ---------------------------------------------------------------------------
extern "C" void kernel_launch(void* const* d_in, const int* in_sizes, int n_in,
                              void* d_out, int out_size)
{
    const float* edge_attr  = (const float*)d_in[0];
    const float* edge_attr2 = (const float*)d_in[1];
    const float* Wp  = (const float*)d_in[2];
    const float* bp  = (const float*)d_in[3];
    const float* W1a = (const float*)d_in[4];
    const float* b1a = (const float*)d_in[5];
    const float* W2a = (const float*)d_in[6];
    const float* b2a = (const float*)d_in[7];
    const float* W1b = (const float*)d_in[8];
    const float* b1b = (const float*)d_in[9];
    const float* W2b = (const float*)d_in[10];
    const float* b2b = (const float*)d_in[11];
    const void* t111 = d_in[12];
    const void* t112 = d_in[13];
    const void* t122 = d_in[14];
    const void* t222 = d_in[15];
    const void* inv1 = d_in[16];
    const void* inv2 = d_in[17];

    int E  = in_sizes[0] / 64;
    int E2 = in_sizes[1] / 64;
    long long T = in_sizes[12] / 3;

    float *Sbase, *M, *P;
    int *cbase;
    cudaGetSymbolAddress((void**)&Sbase, g_S);
    cudaGetSymbolAddress((void**)&M, g_M);
    cudaGetSymbolAddress((void**)&P, g_P);
    cudaGetSymbolAddress((void**)&cbase, g_c);

    cudaFuncSetAttribute(combine_mma, cudaFuncAttributeMaxDynamicSharedMemorySize, CB_SMEM);
    cudaFuncSetAttribute(mlp_mma,     cudaFuncAttributeMaxDynamicSharedMemorySize, ML_SMEM);

    float* out1 = (float*)d_out;
    float* out2 = out1 + (size_t)E * 64;

    detect_kernel<<<1, 32>>>((const int*)t111);
    prep_kernel<<<10, 256>>>(Wp, W1a, W2a, W1b, W2b);

    int sb = (int)((T * 16 + 255) / 256);
    int tiles1 = (E  + 127) / 128;
    int tiles2 = (E2 + 127) / 128;
    int g1 = tiles1 < 1184 ? tiles1 : 1184;
    int g2 = tiles2 < 1184 ? tiles2 : 1184;

    // ---- Phase 1 ----
    {
        float *S0 = Sbase, *S1 = Sbase + (size_t)E * 64, *S2 = Sbase + (size_t)2 * E * 64;
        int *c0 = cbase, *c1 = cbase + E, *c2 = cbase + 2 * E;
        cudaMemsetAsync(Sbase, 0, (size_t)3 * E * 64 * sizeof(float));
        cudaMemsetAsync(cbase, 0, (size_t)3 * E * sizeof(int));

        scatter_kernel<<<sb, 256>>>(t111, 0, T, 2 * T, edge_attr, edge_attr, S0, c0, (int)T);
        scatter_kernel<<<sb, 256>>>(t112, 0, T, 2 * T, edge_attr, edge_attr2, S1, c1, (int)T);
        scatter_kernel<<<sb, 256>>>(t122, 0, T, 2 * T, edge_attr2, edge_attr2, S2, c2, (int)T);

        combine_mma<<<g1, 256, CB_SMEM>>>(S0, S1, S2, c0, c1, c2, 0, bp,
                                          edge_attr, M, P, (long long)E, tiles1);
        mlp_mma<<<g1, 256, ML_SMEM>>>(P, M, inv1, 6, 7, b1a, b2a, out1, (long long)E, tiles1);
    }

    // ---- Phase 2 ----
    {
        float *S0 = Sbase, *S1 = Sbase + (size_t)E2 * 64, *S2 = Sbase + (size_t)2 * E2 * 64;
        int *c0 = cbase, *c1 = cbase + E2, *c2 = cbase + 2 * E2;
        cudaMemsetAsync(Sbase, 0, (size_t)3 * E2 * 64 * sizeof(float));
        cudaMemsetAsync(cbase, 0, (size_t)3 * E2 * sizeof(int));

        scatter_kernel<<<sb, 256>>>(t112, 2 * T, 0, T, out1, out1, S0, c0, (int)T);
        scatter_kernel<<<sb, 256>>>(t122, T, 0, 2 * T, out1, edge_attr2, S1, c1, (int)T);
        scatter_kernel<<<sb, 256>>>(t222, 0, T, 2 * T, edge_attr2, edge_attr2, S2, c2, (int)T);

        combine_mma<<<g2, 256, CB_SMEM>>>(S0, S1, S2, c0, c1, c2, 3, bp,
                                          edge_attr2, M, P, (long long)E2, tiles2);
        mlp_mma<<<g2, 256, ML_SMEM>>>(P, M, inv2, 8, 9, b1b, b2b, out2, (long long)E2, tiles2);
    }
}